// round 14
// baseline (speedup 1.0000x reference)
#include <cuda_runtime.h>
#include <cuda_bf16.h>
#include <cuda_fp16.h>
#include <cstdint>

#define NI   256
#define QK   32
#define BS   4
#define NPIX 4096
#define BM   128
#define BN   64
#define NT   (NPIX / BN)

// ---------------- scratch (16B-aligned) ----------------
__device__ __align__(16) __half         g_Q[BS * NPIX * 32];    // [b][n][32] fp16
__device__ __align__(16) __half         g_K[BS * NPIX * 32];    // [b][n][32] fp16
__device__ __align__(16) __nv_bfloat16  g_V[BS * NI * NPIX];    // [b][c][n] bf16
__device__ __align__(16) __nv_bfloat16  g_Wv[NI * NI];          // V weights bf16
__device__ __align__(16) __half         g_Wqk[64 * NI];         // [32 wq | 32 wk] fp16

// ---------------- helpers ----------------
__device__ __forceinline__ uint32_t smem_u32(const void* p) {
    uint32_t a;
    asm("{ .reg .u64 t; cvta.to.shared.u64 t, %1; cvt.u32.u64 %0, t; }" : "=r"(a) : "l"(p));
    return a;
}
__device__ __forceinline__ uint32_t cvt_bf16x2(float lo, float hi) {
    uint32_t r;
    asm("cvt.rn.bf16x2.f32 %0, %1, %2;" : "=r"(r) : "f"(hi), "f"(lo));
    return r;
}
__device__ __forceinline__ uint32_t cvt_f16x2(float lo, float hi) {
    uint32_t r;
    asm("cvt.rn.f16x2.f32 %0, %1, %2;" : "=r"(r) : "f"(hi), "f"(lo));
    return r;
}
__device__ __forceinline__ void ldsm4(uint32_t* r, uint32_t addr) {
    asm volatile("ldmatrix.sync.aligned.m8n8.x4.shared.b16 {%0,%1,%2,%3}, [%4];"
        : "=r"(r[0]), "=r"(r[1]), "=r"(r[2]), "=r"(r[3]) : "r"(addr));
}
__device__ __forceinline__ void mma_bf16(float* d, const uint32_t* a,
                                         uint32_t b0, uint32_t b1) {
    asm volatile("mma.sync.aligned.m16n8k16.row.col.f32.bf16.bf16.f32 "
        "{%0,%1,%2,%3}, {%4,%5,%6,%7}, {%8,%9}, {%0,%1,%2,%3};"
        : "+f"(d[0]), "+f"(d[1]), "+f"(d[2]), "+f"(d[3])
        : "r"(a[0]), "r"(a[1]), "r"(a[2]), "r"(a[3]), "r"(b0), "r"(b1));
}
__device__ __forceinline__ void mma_fp16(float* d, const uint32_t* a,
                                         uint32_t b0, uint32_t b1) {
    asm volatile("mma.sync.aligned.m16n8k16.row.col.f32.f16.f16.f32 "
        "{%0,%1,%2,%3}, {%4,%5,%6,%7}, {%8,%9}, {%0,%1,%2,%3};"
        : "+f"(d[0]), "+f"(d[1]), "+f"(d[2]), "+f"(d[3])
        : "r"(a[0]), "r"(a[1]), "r"(a[2]), "r"(a[3]), "r"(b0), "r"(b1));
}
#define STS128X(a, r0, r1, r2, r3) \
    asm volatile("st.shared.v4.b32 [%0], {%1,%2,%3,%4};" :: "r"(a), "r"(r0), "r"(r1), "r"(r2), "r"(r3) : "memory")
#define STS32X(a, r0) \
    asm volatile("st.shared.b32 [%0], %1;" :: "r"(a), "r"(r0) : "memory")
__device__ __forceinline__ void cp16(uint32_t dst, const void* src) {
    asm volatile("cp.async.cg.shared.global [%0], [%1], 16;" :: "r"(dst), "l"(src) : "memory");
}

// ---- mbarrier ----
#define MBAR_INIT(a, n) \
    asm volatile("mbarrier.init.shared.b64 [%0], %1;" :: "r"(a), "r"(n) : "memory")
#define MBAR_ARRIVE(a) \
    asm volatile("mbarrier.arrive.shared.b64 _, [%0];" :: "r"(a) : "memory")
#define CP_MBAR_ARRIVE(a) \
    asm volatile("cp.async.mbarrier.arrive.noinc.shared.b64 [%0];" :: "r"(a) : "memory")
#define MBAR_WAIT(a, ph) \
    asm volatile("{ .reg .pred P1; WL%=: mbarrier.try_wait.parity.shared.b64 P1, [%0], %1; @P1 bra WD%=; bra WL%=; WD%=: }" :: "r"(a), "r"(ph) : "memory")

// ---------------------------------------------------------------------------
// Weight converts: wv -> bf16, wq/wk -> fp16 stacked [64][256]
// ---------------------------------------------------------------------------
__global__ void conv_w_kernel(const float* __restrict__ Wv,
                              const float* __restrict__ Wq,
                              const float* __restrict__ Wk) {
    int bid = blockIdx.x;
    if (bid < 64) {
        int i = bid * 256 + threadIdx.x;
        float4 v = reinterpret_cast<const float4*>(Wv)[i];
        uint2 o;
        o.x = cvt_bf16x2(v.x, v.y);
        o.y = cvt_bf16x2(v.z, v.w);
        reinterpret_cast<uint2*>(g_Wv)[i] = o;
    } else {
        int sub = (bid - 64) >> 3;
        int i = ((bid - 64) & 7) * 256 + threadIdx.x;
        const float4* W = reinterpret_cast<const float4*>(sub ? Wk : Wq);
        float4 v = W[i];
        uint2 o;
        o.x = cvt_f16x2(v.x, v.y);
        o.y = cvt_f16x2(v.z, v.w);
        reinterpret_cast<uint2*>(g_Wqk)[sub * 2048 + i] = o;
    }
}

// ---------------------------------------------------------------------------
// Q+K projection via fp16 HMMA (unchanged)
// ---------------------------------------------------------------------------
#define QK_A 0
#define QK_B 5120
#define QK_O 0
#define QK_SMEM 36864

__global__ __launch_bounds__(256) void proj_qk_mma(
    const float* __restrict__ x,
    const float* __restrict__ bq, const float* __restrict__ bk)
{
    __shared__ __align__(16) char smq[QK_SMEM];
    const uint32_t sb = smem_u32(smq);

    const int t = threadIdx.x, w = t >> 5, lane = t & 31;
    const int mband = w & 3, nh = w >> 2;
    const int b = blockIdx.y, n0 = blockIdx.x * 256;

    const int a_r = (lane & 7) + (lane & 8);
    const int a_k = (lane & 16) >> 1;
    const int b_r = (lane & 7) + ((lane & 16) >> 1);
    const int b_k = lane & 8;

    float acc[16][4];
    #pragma unroll
    for (int nt = 0; nt < 16; nt++)
        #pragma unroll
        for (int k = 0; k < 4; k++) acc[nt][k] = 0.f;

    const uint32_t aa = sb + QK_A + (uint32_t)(mband * 16 + a_r) * 80 + a_k * 2;
    const uint32_t bb = sb + QK_B + (uint32_t)(nh * 128 + b_r) * 80 + b_k * 2;

    for (int kc = 0; kc < NI; kc += 32) {
        if (kc) __syncthreads();
        {
            int row = t >> 2, c = t & 3;
            uint4 v = *reinterpret_cast<const uint4*>(g_Wqk + row * NI + kc + c * 8);
            STS128X(sb + QK_A + row * 80 + c * 16, v.x, v.y, v.z, v.w);
        }
        __half* bp = reinterpret_cast<__half*>(smq + QK_B);
        #pragma unroll
        for (int r = 0; r < 8; r++) {
            int fi = t + r * 256;
            int kk = fi >> 6, f4 = fi & 63;
            float4 xv = *reinterpret_cast<const float4*>(
                x + (size_t)(b * NI + kc + kk) * NPIX + n0 + f4 * 4);
            bp[(f4 * 4 + 0) * 40 + kk] = __float2half_rn(xv.x);
            bp[(f4 * 4 + 1) * 40 + kk] = __float2half_rn(xv.y);
            bp[(f4 * 4 + 2) * 40 + kk] = __float2half_rn(xv.z);
            bp[(f4 * 4 + 3) * 40 + kk] = __float2half_rn(xv.w);
        }
        __syncthreads();

        #pragma unroll
        for (int ks = 0; ks < 2; ks++) {
            uint32_t af[4];
            ldsm4(af, aa + ks * 32);
            #pragma unroll
            for (int ntp = 0; ntp < 8; ntp++) {
                uint32_t bf[4];
                ldsm4(bf, bb + ntp * (16 * 80) + ks * 32);
                mma_fp16(acc[2 * ntp],     af, bf[0], bf[1]);
                mma_fp16(acc[2 * ntp + 1], af, bf[2], bf[3]);
            }
        }
    }
    __syncthreads();

    {
        int row = mband * 16 + (lane >> 2);
        float bias0 = (row < 32) ? bq[row] : bk[row - 32];
        float bias8 = (row + 8 < 32) ? bq[row + 8] : bk[row + 8 - 32];
        __half* st = reinterpret_cast<__half*>(smq + QK_O);
        #pragma unroll
        for (int nt = 0; nt < 16; nt++) {
            int pix = nh * 128 + nt * 8 + 2 * (lane & 3);
            st[pix * 72 + row]           = __float2half_rn(acc[nt][0] + bias0);
            st[(pix + 1) * 72 + row]     = __float2half_rn(acc[nt][1] + bias0);
            st[pix * 72 + row + 8]       = __float2half_rn(acc[nt][2] + bias8);
            st[(pix + 1) * 72 + row + 8] = __float2half_rn(acc[nt][3] + bias8);
        }
    }
    __syncthreads();

    #pragma unroll
    for (int r = 0; r < 8; r++) {
        int fi = t + r * 256;
        int pix = fi >> 3, g = fi & 7;
        uint4 v = *reinterpret_cast<const uint4*>(smq + QK_O + pix * 144 + g * 16);
        size_t nbase = (size_t)(b * NPIX + n0 + pix) * 32;
        if (g < 4)
            reinterpret_cast<uint4*>(g_Q + nbase)[g] = v;
        else
            reinterpret_cast<uint4*>(g_K + nbase)[g - 4] = v;
    }
}

// ---------------------------------------------------------------------------
// V projection via bf16 HMMA (unchanged)
// ---------------------------------------------------------------------------
#define PV_A 0
#define PV_B 20480
#define PV_D 0
#define PV_SMEM 36864

__global__ __launch_bounds__(256) void proj_v_kernel(
    const float* __restrict__ x, const float* __restrict__ bv)
{
    __shared__ __align__(16) char smv[PV_SMEM];
    const uint32_t sb = smem_u32(smv);

    const int t = threadIdx.x, w = t >> 5, lane = t & 31;
    const int b = blockIdx.y, n0 = blockIdx.x * 64;

    const int a_r = (lane & 7) + (lane & 8);
    const int a_k = (lane & 16) >> 1;
    const int b_r = (lane & 7) + ((lane & 16) >> 1);
    const int b_k = lane & 8;

    float acc[2][8][4];
    #pragma unroll
    for (int mi = 0; mi < 2; mi++)
        #pragma unroll
        for (int nt = 0; nt < 8; nt++)
            #pragma unroll
            for (int k = 0; k < 4; k++) acc[mi][nt][k] = 0.f;

    const uint32_t aa = sb + PV_A + (uint32_t)(w * 32 + a_r) * 80 + a_k * 2;
    const uint32_t bb = sb + PV_B + (uint32_t)b_r * 80 + b_k * 2;

    for (int kc = 0; kc < NI; kc += 32) {
        if (kc) __syncthreads();
        #pragma unroll
        for (int r = 0; r < 4; r++) {
            int fi = t + r * 256;
            int row = fi >> 2, c = fi & 3;
            uint4 v = *reinterpret_cast<const uint4*>(g_Wv + row * NI + kc + c * 8);
            STS128X(sb + PV_A + row * 80 + c * 16, v.x, v.y, v.z, v.w);
        }
        #pragma unroll
        for (int r = 0; r < 2; r++) {
            int fi = t + r * 256;
            int kk = fi >> 4, f4 = fi & 15;
            float4 xv = *reinterpret_cast<const float4*>(
                x + (size_t)(b * NI + kc + kk) * NPIX + n0 + f4 * 4);
            __nv_bfloat16* bp = reinterpret_cast<__nv_bfloat16*>(smv + PV_B);
            bp[(f4 * 4 + 0) * 40 + kk] = __float2bfloat16(xv.x);
            bp[(f4 * 4 + 1) * 40 + kk] = __float2bfloat16(xv.y);
            bp[(f4 * 4 + 2) * 40 + kk] = __float2bfloat16(xv.z);
            bp[(f4 * 4 + 3) * 40 + kk] = __float2bfloat16(xv.w);
        }
        __syncthreads();

        #pragma unroll
        for (int ks = 0; ks < 2; ks++) {
            uint32_t af[2][4];
            ldsm4(af[0], aa + ks * 32);
            ldsm4(af[1], aa + 16 * 80 + ks * 32);
            #pragma unroll
            for (int ntp = 0; ntp < 4; ntp++) {
                uint32_t bf[4];
                ldsm4(bf, bb + ntp * (16 * 80) + ks * 32);
                #pragma unroll
                for (int mi = 0; mi < 2; mi++) {
                    mma_bf16(acc[mi][2 * ntp],     af[mi], bf[0], bf[1]);
                    mma_bf16(acc[mi][2 * ntp + 1], af[mi], bf[2], bf[3]);
                }
            }
        }
    }
    __syncthreads();

    {
        int r0 = lane >> 2, cp = 2 * (lane & 3);
        #pragma unroll
        for (int mi = 0; mi < 2; mi++) {
            int c = w * 32 + mi * 16 + r0;
            float bva = bv[c], bvb = bv[c + 8];
            #pragma unroll
            for (int nt = 0; nt < 8; nt++) {
                int n = nt * 8 + cp;
                STS32X(sb + PV_D + (uint32_t)c * 144 + n * 2,
                       cvt_bf16x2(acc[mi][nt][0] + bva, acc[mi][nt][1] + bva));
                STS32X(sb + PV_D + (uint32_t)(c + 8) * 144 + n * 2,
                       cvt_bf16x2(acc[mi][nt][2] + bvb, acc[mi][nt][3] + bvb));
            }
        }
    }
    __syncthreads();

    #pragma unroll
    for (int r = 0; r < 8; r++) {
        int fi = t + r * 256;
        int row = fi >> 3, c4 = fi & 7;
        uint4 v = *reinterpret_cast<const uint4*>(smv + PV_D + row * 144 + c4 * 16);
        *reinterpret_cast<uint4*>(
            g_V + (size_t)(b * NI + row) * NPIX + n0 + c4 * 8) = v;
    }
}

// ---------------------------------------------------------------------------
// HMMA flash attention, mbarrier slot ring (NO per-tile __syncthreads).
// 8 warps; warp w owns q rows [w*16,w*16+16), all 64 j, all 256 ch (register P).
// 4-slot K/V ring; full[s] (256 cp.async.noinc arrivals) / empty[s] (256
// arrivals); warps drift up to ~3 tiles -> decorrelated stalls.
// smem: Q[128][80B] @0 | slot s @10240+s*41984: K[64][80B] + V[256][144B]
//       mbarriers @178176 (full[0..3], empty[0..3])
// ---------------------------------------------------------------------------
#define OFF_Q    0
#define OFF_SLOT 10240
#define SLOT_SZ  41984
#define SLOT_V   5120
#define OFF_B    178176
#define SMEM_BYTES (OFF_B + 64)

__global__ __launch_bounds__(256, 1) void attn_kernel(
    const float* __restrict__ x, const float* __restrict__ gamma,
    float* __restrict__ out)
{
    extern __shared__ __align__(16) char smraw[];
    const uint32_t sb = smem_u32(smraw);

    const int tid = threadIdx.x;
    const int w = tid >> 5, lane = tid & 31;
    const int b = blockIdx.y, n0 = blockIdx.x * BM;

    const int a_r = (lane & 7) + (lane & 8);
    const int a_k = (lane & 16) >> 1;
    const int b_r = (lane & 7) + ((lane & 16) >> 1);
    const int b_k = lane & 8;

    const uint32_t mb_full  = sb + OFF_B;
    const uint32_t mb_empty = sb + OFF_B + 32;

    if (tid == 0) {
        #pragma unroll
        for (int s = 0; s < 4; s++) {
            MBAR_INIT(mb_full + s * 8, 256);
            MBAR_INIT(mb_empty + s * 8, 256);
        }
    }

    // ---- Q tile [128][32] fp16 ----
    {
        const uint4* Qg = reinterpret_cast<const uint4*>(g_Q + (size_t)(b * NPIX + n0) * 32);
        #pragma unroll
        for (int r = 0; r < 2; r++) {
            int fi = tid + r * 256;
            int row = fi >> 2, c = fi & 3;
            uint4 v = Qg[fi];
            STS128X(sb + OFF_Q + row * 80 + c * 16, v.x, v.y, v.z, v.w);
        }
    }
    __syncthreads();   // Q visible + mbarriers initialized (only CTA-wide sync)

    // per-thread tile loader into slot (jt & 3)
    auto load_tile = [&](int jt) {
        const uint32_t slot = sb + OFF_SLOT + (uint32_t)(jt & 3) * SLOT_SZ;
        {
            const char* Kg = reinterpret_cast<const char*>(
                g_K + (size_t)(b * NPIX + jt * BN) * 32);
            int row = tid >> 2, c = tid & 3;
            cp16(slot + row * 80 + c * 16, Kg + row * 64 + c * 16);
        }
        #pragma unroll
        for (int r = 0; r < 8; r++) {
            int fi = tid + r * 256;
            int cc = fi >> 3, g = fi & 7;
            cp16(slot + SLOT_V + cc * 144 + g * 16,
                 reinterpret_cast<const char*>(
                     g_V + (size_t)(b * NI + cc) * NPIX + jt * BN) + g * 16);
        }
        CP_MBAR_ARRIVE(mb_full + (jt & 3) * 8);
    };

    // prologue: fill all 4 slots
    #pragma unroll
    for (int s = 0; s < 4; s++) load_tile(s);

    // Q A-fragments (invariant)
    uint32_t af[2][4];
    #pragma unroll
    for (int ks = 0; ks < 2; ks++)
        ldsm4(af[ks], sb + OFF_Q + (uint32_t)(w * 16 + a_r) * 80 + a_k * 2 + ks * 32);

    float oacc[32][4];
    #pragma unroll
    for (int ct = 0; ct < 32; ct++)
        #pragma unroll
        for (int k = 0; k < 4; k++) oacc[ct][k] = 0.f;
    float lacc[2] = {0.f, 0.f};

    #pragma unroll 1
    for (int jt = 0; jt < NT; jt++) {
        const int s = jt & 3;
        const int ph = (jt >> 2) & 1;
        const uint32_t slot = sb + OFF_SLOT + (uint32_t)s * SLOT_SZ;

        MBAR_WAIT(mb_full + s * 8, ph);

        // ---- MMA1 (fp16): S = Q K^T (16q x 64j), k=32 ----
        float sacc[8][4];
        #pragma unroll
        for (int ni = 0; ni < 8; ni++)
            #pragma unroll
            for (int k = 0; k < 4; k++) sacc[ni][k] = 0.f;
        {
            const uint32_t kb = slot + (uint32_t)b_r * 80 + b_k * 2;
            #pragma unroll
            for (int ks = 0; ks < 2; ks++) {
                uint32_t bfn[4][4];
                #pragma unroll
                for (int np = 0; np < 4; np++)
                    ldsm4(bfn[np], kb + np * (16 * 80) + ks * 32);
                #pragma unroll
                for (int ni = 0; ni < 8; ni++)
                    mma_fp16(sacc[ni], af[ks], bfn[ni >> 1][(ni & 1) * 2],
                             bfn[ni >> 1][(ni & 1) * 2 + 1]);
            }
        }

        // ---- exp in registers + row sums + pack P A-frags ----
        uint32_t pa[4][4];
        #pragma unroll
        for (int g = 0; g < 4; g++) {
            float e0 = __expf(sacc[2 * g][0]),     e1 = __expf(sacc[2 * g][1]);
            float e2 = __expf(sacc[2 * g][2]),     e3 = __expf(sacc[2 * g][3]);
            float e4 = __expf(sacc[2 * g + 1][0]), e5 = __expf(sacc[2 * g + 1][1]);
            float e6 = __expf(sacc[2 * g + 1][2]), e7 = __expf(sacc[2 * g + 1][3]);
            lacc[0] += e0 + e1 + e4 + e5;
            lacc[1] += e2 + e3 + e6 + e7;
            pa[g][0] = cvt_bf16x2(e0, e1);
            pa[g][1] = cvt_bf16x2(e2, e3);
            pa[g][2] = cvt_bf16x2(e4, e5);
            pa[g][3] = cvt_bf16x2(e6, e7);
        }

        // ---- MMA2 (bf16): O += P @ V^T over all 256 ch, k=64 ----
        {
            const uint32_t vb = slot + SLOT_V + (uint32_t)b_r * 144 + b_k * 2;
            #pragma unroll
            for (int g = 0; g < 4; g++)
                #pragma unroll
                for (int ntv = 0; ntv < 16; ntv++) {
                    uint32_t bf[4];
                    ldsm4(bf, vb + ntv * (16 * 144) + g * 32);
                    mma_bf16(oacc[2 * ntv],     pa[g], bf[0], bf[1]);
                    mma_bf16(oacc[2 * ntv + 1], pa[g], bf[2], bf[3]);
                }
        }

        MBAR_ARRIVE(mb_empty + s * 8);

        // refill this slot with tile jt+4
        if (jt + 4 < NT) {
            MBAR_WAIT(mb_empty + s * 8, ph);
            load_tile(jt + 4);
        }
    }

    // ---- row-sum reduce (intra-quad; warp owns full j) ----
    float linv[2];
    #pragma unroll
    for (int rh = 0; rh < 2; rh++) {
        float v = lacc[rh];
        v += __shfl_xor_sync(0xffffffffu, v, 1);
        v += __shfl_xor_sync(0xffffffffu, v, 2);
        linv[rh] = 1.f / v;
    }

    // ---- epilogue: out = gamma*O/l + x ----
    {
        int q0 = n0 + w * 16 + (lane >> 2);
        #pragma unroll
        for (int ct = 0; ct < 32; ct++) {
            int c0 = ct * 8 + 2 * (lane & 3);
            float ga = gamma[c0], gb = gamma[c0 + 1];
            size_t i00 = (size_t)(b * NI + c0) * NPIX + q0;
            out[i00]            = ga * oacc[ct][0] * linv[0] + x[i00];
            out[i00 + NPIX]     = gb * oacc[ct][1] * linv[0] + x[i00 + NPIX];
            out[i00 + 8]        = ga * oacc[ct][2] * linv[1] + x[i00 + 8];
            out[i00 + NPIX + 8] = gb * oacc[ct][3] * linv[1] + x[i00 + NPIX + 8];
        }
    }
}

// ---------------------------------------------------------------------------
extern "C" void kernel_launch(void* const* d_in, const int* in_sizes, int n_in,
                              void* d_out, int out_size)
{
    const float* x     = (const float*)d_in[0];
    const float* wq    = (const float*)d_in[1];
    const float* bq    = (const float*)d_in[2];
    const float* wk    = (const float*)d_in[3];
    const float* bk    = (const float*)d_in[4];
    const float* wv    = (const float*)d_in[5];
    const float* bv    = (const float*)d_in[6];
    const float* gamma = (const float*)d_in[7];
    float* out = (float*)d_out;

    cudaFuncSetAttribute(attn_kernel,
                         cudaFuncAttributeMaxDynamicSharedMemorySize, SMEM_BYTES);

    conv_w_kernel<<<80, 256>>>(wv, wq, wk);
    proj_qk_mma<<<dim3(16, BS), 256>>>(x, bq, bk);
    proj_v_kernel<<<dim3(64, BS), 256>>>(x, bv);
    attn_kernel<<<dim3(NPIX / BM, BS), 256, SMEM_BYTES>>>(x, gamma, out);
}

// round 17
// speedup vs baseline: 1.4445x; 1.4445x over previous
#include <cuda_runtime.h>
#include <cuda_bf16.h>
#include <cuda_fp16.h>
#include <cstdint>

#define NI   256
#define QK   32
#define BS   4
#define NPIX 4096
#define BM   128
#define BN   64
#define NT   (NPIX / BN)

// ---------------- scratch (16B-aligned) ----------------
__device__ __align__(16) __half         g_Q[BS * NPIX * 32];    // [b][n][32] fp16
__device__ __align__(16) __half         g_K[BS * NPIX * 32];    // [b][n][32] fp16
__device__ __align__(16) __nv_bfloat16  g_V[BS * NI * NPIX];    // [b][c][n] bf16

// ---------------- helpers ----------------
__device__ __forceinline__ uint32_t smem_u32(const void* p) {
    uint32_t a;
    asm("{ .reg .u64 t; cvta.to.shared.u64 t, %1; cvt.u32.u64 %0, t; }" : "=r"(a) : "l"(p));
    return a;
}
__device__ __forceinline__ uint32_t cvt_bf16x2(float lo, float hi) {
    uint32_t r;
    asm("cvt.rn.bf16x2.f32 %0, %1, %2;" : "=r"(r) : "f"(hi), "f"(lo));
    return r;
}
__device__ __forceinline__ uint32_t cvt_f16x2(float lo, float hi) {
    uint32_t r;
    asm("cvt.rn.f16x2.f32 %0, %1, %2;" : "=r"(r) : "f"(hi), "f"(lo));
    return r;
}
__device__ __forceinline__ void ldsm4(uint32_t* r, uint32_t addr) {
    asm volatile("ldmatrix.sync.aligned.m8n8.x4.shared.b16 {%0,%1,%2,%3}, [%4];"
        : "=r"(r[0]), "=r"(r[1]), "=r"(r[2]), "=r"(r[3]) : "r"(addr));
}
__device__ __forceinline__ void mma_bf16(float* d, const uint32_t* a,
                                         uint32_t b0, uint32_t b1) {
    asm volatile("mma.sync.aligned.m16n8k16.row.col.f32.bf16.bf16.f32 "
        "{%0,%1,%2,%3}, {%4,%5,%6,%7}, {%8,%9}, {%0,%1,%2,%3};"
        : "+f"(d[0]), "+f"(d[1]), "+f"(d[2]), "+f"(d[3])
        : "r"(a[0]), "r"(a[1]), "r"(a[2]), "r"(a[3]), "r"(b0), "r"(b1));
}
__device__ __forceinline__ void mma_fp16(float* d, const uint32_t* a,
                                         uint32_t b0, uint32_t b1) {
    asm volatile("mma.sync.aligned.m16n8k16.row.col.f32.f16.f16.f32 "
        "{%0,%1,%2,%3}, {%4,%5,%6,%7}, {%8,%9}, {%0,%1,%2,%3};"
        : "+f"(d[0]), "+f"(d[1]), "+f"(d[2]), "+f"(d[3])
        : "r"(a[0]), "r"(a[1]), "r"(a[2]), "r"(a[3]), "r"(b0), "r"(b1));
}
#define STS128X(a, r0, r1, r2, r3) \
    asm volatile("st.shared.v4.b32 [%0], {%1,%2,%3,%4};" :: "r"(a), "r"(r0), "r"(r1), "r"(r2), "r"(r3) : "memory")
#define STS32X(a, r0) \
    asm volatile("st.shared.b32 [%0], %1;" :: "r"(a), "r"(r0) : "memory")
__device__ __forceinline__ void cp16(uint32_t dst, const void* src) {
    asm volatile("cp.async.cg.shared.global [%0], [%1], 16;" :: "r"(dst), "l"(src) : "memory");
}
#define CP_COMMIT() asm volatile("cp.async.commit_group;" ::: "memory")
#define CP_WAIT0()  asm volatile("cp.async.wait_group 0;" ::: "memory")

// ---------------------------------------------------------------------------
// Merged projection kernel: ONE launch computes Q, K (fp16 HMMA) and V (bf16
// HMMA), converting fp32 weights inline during smem staging (no conv_w pass).
// grid (80, BS): blockIdx.x < 16  -> Q+K tile (n0 = x*256)
//                blockIdx.x >= 16 -> V tile   (n0 = (x-16)*64)
// ---------------------------------------------------------------------------
#define QK_A 0
#define QK_B 5120
#define QK_O 0
#define PV_A 0
#define PV_B 20480
#define PV_D 0
#define PRJ_SMEM 36864

__global__ __launch_bounds__(256) void proj_all(
    const float* __restrict__ x,
    const float* __restrict__ Wq, const float* __restrict__ bq,
    const float* __restrict__ Wk, const float* __restrict__ bk,
    const float* __restrict__ Wv, const float* __restrict__ bv)
{
    __shared__ __align__(16) char smm[PRJ_SMEM];
    const uint32_t sb = smem_u32(smm);

    const int t = threadIdx.x, w = t >> 5, lane = t & 31;
    const int b = blockIdx.y;

    const int a_r = (lane & 7) + (lane & 8);
    const int a_k = (lane & 16) >> 1;
    const int b_r = (lane & 7) + ((lane & 16) >> 1);
    const int b_k = lane & 8;

    if (blockIdx.x < 16) {
        // ================= Q+K path: M=64 (32q|32k) x N=256 pixels =========
        const int mband = w & 3, nh = w >> 2;
        const int n0 = blockIdx.x * 256;

        float acc[16][4];
        #pragma unroll
        for (int nt = 0; nt < 16; nt++)
            #pragma unroll
            for (int k = 0; k < 4; k++) acc[nt][k] = 0.f;

        const uint32_t aa = sb + QK_A + (uint32_t)(mband * 16 + a_r) * 80 + a_k * 2;
        const uint32_t bb = sb + QK_B + (uint32_t)(nh * 128 + b_r) * 80 + b_k * 2;

        for (int kc = 0; kc < NI; kc += 32) {
            if (kc) __syncthreads();
            // A: rows 0-31 = Wq, 32-63 = Wk, fp32 -> fp16 inline
            {
                int row = t >> 2, c = t & 3;
                const float* Wrow = (row < 32) ? (Wq + (size_t)row * NI)
                                               : (Wk + (size_t)(row - 32) * NI);
                float4 w0 = *reinterpret_cast<const float4*>(Wrow + kc + c * 8);
                float4 w1 = *reinterpret_cast<const float4*>(Wrow + kc + c * 8 + 4);
                STS128X(sb + QK_A + row * 80 + c * 16,
                        cvt_f16x2(w0.x, w0.y), cvt_f16x2(w0.z, w0.w),
                        cvt_f16x2(w1.x, w1.y), cvt_f16x2(w1.z, w1.w));
            }
            // B: x [kc..kc+31][n0..n0+255] fp32 -> fp16 [pix][k]
            __half* bp = reinterpret_cast<__half*>(smm + QK_B);
            #pragma unroll
            for (int r = 0; r < 8; r++) {
                int fi = t + r * 256;
                int kk = fi >> 6, f4 = fi & 63;
                float4 xv = *reinterpret_cast<const float4*>(
                    x + (size_t)(b * NI + kc + kk) * NPIX + n0 + f4 * 4);
                bp[(f4 * 4 + 0) * 40 + kk] = __float2half_rn(xv.x);
                bp[(f4 * 4 + 1) * 40 + kk] = __float2half_rn(xv.y);
                bp[(f4 * 4 + 2) * 40 + kk] = __float2half_rn(xv.z);
                bp[(f4 * 4 + 3) * 40 + kk] = __float2half_rn(xv.w);
            }
            __syncthreads();

            #pragma unroll
            for (int ks = 0; ks < 2; ks++) {
                uint32_t af[4];
                ldsm4(af, aa + ks * 32);
                #pragma unroll
                for (int ntp = 0; ntp < 8; ntp++) {
                    uint32_t bf[4];
                    ldsm4(bf, bb + ntp * (16 * 80) + ks * 32);
                    mma_fp16(acc[2 * ntp],     af, bf[0], bf[1]);
                    mma_fp16(acc[2 * ntp + 1], af, bf[2], bf[3]);
                }
            }
        }
        __syncthreads();

        // bias + stage [256 pix][72]h (col = out channel: 0-31 q, 32-63 k)
        {
            int row = mband * 16 + (lane >> 2);
            float bias0 = (row < 32) ? bq[row] : bk[row - 32];
            float bias8 = (row + 8 < 32) ? bq[row + 8] : bk[row + 8 - 32];
            __half* st = reinterpret_cast<__half*>(smm + QK_O);
            #pragma unroll
            for (int nt = 0; nt < 16; nt++) {
                int pix = nh * 128 + nt * 8 + 2 * (lane & 3);
                st[pix * 72 + row]           = __float2half_rn(acc[nt][0] + bias0);
                st[(pix + 1) * 72 + row]     = __float2half_rn(acc[nt][1] + bias0);
                st[pix * 72 + row + 8]       = __float2half_rn(acc[nt][2] + bias8);
                st[(pix + 1) * 72 + row + 8] = __float2half_rn(acc[nt][3] + bias8);
            }
        }
        __syncthreads();

        #pragma unroll
        for (int r = 0; r < 8; r++) {
            int fi = t + r * 256;
            int pix = fi >> 3, g = fi & 7;
            uint4 v = *reinterpret_cast<const uint4*>(smm + QK_O + pix * 144 + g * 16);
            size_t nbase = (size_t)(b * NPIX + n0 + pix) * 32;
            if (g < 4)
                reinterpret_cast<uint4*>(g_Q + nbase)[g] = v;
            else
                reinterpret_cast<uint4*>(g_K + nbase)[g - 4] = v;
        }
    } else {
        // ================= V path: M=256 channels x N=64 pixels ============
        const int n0 = (blockIdx.x - 16) * 64;

        float acc[2][8][4];
        #pragma unroll
        for (int mi = 0; mi < 2; mi++)
            #pragma unroll
            for (int nt = 0; nt < 8; nt++)
                #pragma unroll
                for (int k = 0; k < 4; k++) acc[mi][nt][k] = 0.f;

        const uint32_t aa = sb + PV_A + (uint32_t)(w * 32 + a_r) * 80 + a_k * 2;
        const uint32_t bb = sb + PV_B + (uint32_t)b_r * 80 + b_k * 2;

        for (int kc = 0; kc < NI; kc += 32) {
            if (kc) __syncthreads();
            // A: Wv rows [256][kc..kc+31] fp32 -> bf16 inline
            #pragma unroll
            for (int r = 0; r < 4; r++) {
                int fi = t + r * 256;
                int row = fi >> 2, c = fi & 3;
                float4 w0 = *reinterpret_cast<const float4*>(
                    Wv + (size_t)row * NI + kc + c * 8);
                float4 w1 = *reinterpret_cast<const float4*>(
                    Wv + (size_t)row * NI + kc + c * 8 + 4);
                STS128X(sb + PV_A + row * 80 + c * 16,
                        cvt_bf16x2(w0.x, w0.y), cvt_bf16x2(w0.z, w0.w),
                        cvt_bf16x2(w1.x, w1.y), cvt_bf16x2(w1.z, w1.w));
            }
            // B: x [kc..kc+31][n0..n0+63] fp32 -> bf16 [pix][k]
            #pragma unroll
            for (int r = 0; r < 2; r++) {
                int fi = t + r * 256;
                int kk = fi >> 4, f4 = fi & 15;
                float4 xv = *reinterpret_cast<const float4*>(
                    x + (size_t)(b * NI + kc + kk) * NPIX + n0 + f4 * 4);
                __nv_bfloat16* bp = reinterpret_cast<__nv_bfloat16*>(smm + PV_B);
                bp[(f4 * 4 + 0) * 40 + kk] = __float2bfloat16(xv.x);
                bp[(f4 * 4 + 1) * 40 + kk] = __float2bfloat16(xv.y);
                bp[(f4 * 4 + 2) * 40 + kk] = __float2bfloat16(xv.z);
                bp[(f4 * 4 + 3) * 40 + kk] = __float2bfloat16(xv.w);
            }
            __syncthreads();

            #pragma unroll
            for (int ks = 0; ks < 2; ks++) {
                uint32_t af[2][4];
                ldsm4(af[0], aa + ks * 32);
                ldsm4(af[1], aa + 16 * 80 + ks * 32);
                #pragma unroll
                for (int ntp = 0; ntp < 4; ntp++) {
                    uint32_t bf[4];
                    ldsm4(bf, bb + ntp * (16 * 80) + ks * 32);
                    #pragma unroll
                    for (int mi = 0; mi < 2; mi++) {
                        mma_bf16(acc[mi][2 * ntp],     af[mi], bf[0], bf[1]);
                        mma_bf16(acc[mi][2 * ntp + 1], af[mi], bf[2], bf[3]);
                    }
                }
            }
        }
        __syncthreads();

        // bias + stage [256 c][72]bf16 (144B rows)
        {
            int r0 = lane >> 2, cp = 2 * (lane & 3);
            #pragma unroll
            for (int mi = 0; mi < 2; mi++) {
                int c = w * 32 + mi * 16 + r0;
                float bva = bv[c], bvb = bv[c + 8];
                #pragma unroll
                for (int nt = 0; nt < 8; nt++) {
                    int n = nt * 8 + cp;
                    STS32X(sb + PV_D + (uint32_t)c * 144 + n * 2,
                           cvt_bf16x2(acc[mi][nt][0] + bva, acc[mi][nt][1] + bva));
                    STS32X(sb + PV_D + (uint32_t)(c + 8) * 144 + n * 2,
                           cvt_bf16x2(acc[mi][nt][2] + bvb, acc[mi][nt][3] + bvb));
                }
            }
        }
        __syncthreads();

        #pragma unroll
        for (int r = 0; r < 8; r++) {
            int fi = t + r * 256;
            int row = fi >> 3, c4 = fi & 7;
            uint4 v = *reinterpret_cast<const uint4*>(smm + PV_D + row * 144 + c4 * 16);
            *reinterpret_cast<uint4*>(
                g_V + (size_t)(b * NI + row) * NPIX + n0 + c4 * 8) = v;
        }
    }
}

// ---------------------------------------------------------------------------
// HMMA flash attention (round-8 version, best measured: register-resident P).
// 8 warps; warp w owns q rows [w*16, w*16+16), all 64 j, all 256 channels.
// smem: sQ[128][40]h @0 | K0 @10240, K1 @15360 ([64][40]h)
//       V0 @20480, V1 @57344 ([256 c][72 j]bf16 stride 144)
// ---------------------------------------------------------------------------
#define OFF_Q  0
#define OFF_K0 10240
#define OFF_K1 15360
#define OFF_V0 20480
#define OFF_V1 57344
#define SMEM_BYTES 94208

__global__ __launch_bounds__(256, 1) void attn_kernel(
    const float* __restrict__ x, const float* __restrict__ gamma,
    float* __restrict__ out)
{
    extern __shared__ __align__(16) char smraw[];
    const uint32_t sb = smem_u32(smraw);

    const int tid = threadIdx.x;
    const int w = tid >> 5, lane = tid & 31;
    const int b = blockIdx.y, n0 = blockIdx.x * BM;

    const int a_r = (lane & 7) + (lane & 8);
    const int a_k = (lane & 16) >> 1;
    const int b_r = (lane & 7) + ((lane & 16) >> 1);
    const int b_k = lane & 8;

    // ---- Q tile [128][32] fp16 ----
    {
        const uint4* Qg = reinterpret_cast<const uint4*>(g_Q + (size_t)(b * NPIX + n0) * 32);
        #pragma unroll
        for (int r = 0; r < 2; r++) {
            int fi = tid + r * 256;
            int row = fi >> 2, c = fi & 3;
            uint4 v = Qg[fi];
            STS128X(sb + OFF_Q + row * 80 + c * 16, v.x, v.y, v.z, v.w);
        }
    }

    // prefetch tile 0 (K + V)
    {
        const char* Kg = reinterpret_cast<const char*>(g_K + (size_t)(b * NPIX) * 32);
        int row = tid >> 2, c = tid & 3;
        cp16(sb + OFF_K0 + row * 80 + c * 16, Kg + row * 64 + c * 16);
        #pragma unroll
        for (int r = 0; r < 8; r++) {
            int fi = tid + r * 256;
            int cc = fi >> 3, g = fi & 7;
            cp16(sb + OFF_V0 + cc * 144 + g * 16,
                 reinterpret_cast<const char*>(g_V + (size_t)(b * NI + cc) * NPIX) + g * 16);
        }
        CP_COMMIT();
    }
    __syncthreads();

    // Q A-fragments: loaded once (invariant over key tiles)
    uint32_t af[2][4];
    {
        const uint32_t qa_off = sb + OFF_Q + (uint32_t)(w * 16 + a_r) * 80 + a_k * 2;
        ldsm4(af[0], qa_off);
        ldsm4(af[1], qa_off + 32);
    }

    const uint32_t kb_base[2] = {
        sb + OFF_K0 + (uint32_t)b_r * 80 + b_k * 2,
        sb + OFF_K1 + (uint32_t)b_r * 80 + b_k * 2 };
    const uint32_t vb_base[2] = {
        sb + OFF_V0 + (uint32_t)b_r * 144 + b_k * 2,
        sb + OFF_V1 + (uint32_t)b_r * 144 + b_k * 2 };

    float oacc[32][4];
    #pragma unroll
    for (int ct = 0; ct < 32; ct++)
        #pragma unroll
        for (int k = 0; k < 4; k++) oacc[ct][k] = 0.f;
    float lacc[2] = {0.f, 0.f};

    #pragma unroll 1
    for (int jt = 0; jt < NT; jt++) {
        const int buf = jt & 1;
        CP_WAIT0();
        __syncthreads();

        if (jt + 1 < NT) {
            const int j1 = (jt + 1) * BN, nb = buf ^ 1;
            const char* Kg = reinterpret_cast<const char*>(g_K + (size_t)(b * NPIX + j1) * 32);
            int row = tid >> 2, c = tid & 3;
            cp16(sb + (nb ? OFF_K1 : OFF_K0) + row * 80 + c * 16, Kg + row * 64 + c * 16);
            #pragma unroll
            for (int r = 0; r < 8; r++) {
                int fi = tid + r * 256;
                int cc = fi >> 3, g = fi & 7;
                cp16(sb + (nb ? OFF_V1 : OFF_V0) + cc * 144 + g * 16,
                     reinterpret_cast<const char*>(
                         g_V + (size_t)(b * NI + cc) * NPIX + j1) + g * 16);
            }
            CP_COMMIT();
        }

        // ---- MMA1 (fp16): S = Q K^T, per-warp 16q x 64j, k=32 ----
        float sacc[8][4];
        #pragma unroll
        for (int ni = 0; ni < 8; ni++)
            #pragma unroll
            for (int k = 0; k < 4; k++) sacc[ni][k] = 0.f;

        #pragma unroll
        for (int ks = 0; ks < 2; ks++) {
            uint32_t bfn[4][4];
            #pragma unroll
            for (int np = 0; np < 4; np++)
                ldsm4(bfn[np], kb_base[buf] + np * (16 * 80) + ks * 32);
            #pragma unroll
            for (int ni = 0; ni < 8; ni++)
                mma_fp16(sacc[ni], af[ks], bfn[ni >> 1][(ni & 1) * 2],
                         bfn[ni >> 1][(ni & 1) * 2 + 1]);
        }

        // ---- exp in registers + row sums ----
        #pragma unroll
        for (int ni = 0; ni < 8; ni++) {
            float e0 = __expf(sacc[ni][0]);
            float e1 = __expf(sacc[ni][1]);
            float e2 = __expf(sacc[ni][2]);
            float e3 = __expf(sacc[ni][3]);
            lacc[0] += e0 + e1;
            lacc[1] += e2 + e3;
            sacc[ni][0] = e0; sacc[ni][1] = e1;
            sacc[ni][2] = e2; sacc[ni][3] = e3;
        }

        // ---- MMA2 (bf16): O += P @ V^T; P packed from S accumulators ----
        #pragma unroll
        for (int ks2 = 0; ks2 < 4; ks2++) {
            uint32_t pa[4];
            pa[0] = cvt_bf16x2(sacc[2 * ks2][0],     sacc[2 * ks2][1]);
            pa[1] = cvt_bf16x2(sacc[2 * ks2][2],     sacc[2 * ks2][3]);
            pa[2] = cvt_bf16x2(sacc[2 * ks2 + 1][0], sacc[2 * ks2 + 1][1]);
            pa[3] = cvt_bf16x2(sacc[2 * ks2 + 1][2], sacc[2 * ks2 + 1][3]);
            #pragma unroll
            for (int ntp = 0; ntp < 16; ntp++) {
                uint32_t bf[4];
                ldsm4(bf, vb_base[buf] + ntp * (16 * 144) + ks2 * 32);
                mma_bf16(oacc[2 * ntp],     pa, bf[0], bf[1]);
                mma_bf16(oacc[2 * ntp + 1], pa, bf[2], bf[3]);
            }
        }
    }

    // ---- row-sum reduce (intra-quad) ----
    float linv[2];
    #pragma unroll
    for (int rh = 0; rh < 2; rh++) {
        float v = lacc[rh];
        v += __shfl_xor_sync(0xffffffffu, v, 1);
        v += __shfl_xor_sync(0xffffffffu, v, 2);
        linv[rh] = 1.f / v;
    }

    // ---- epilogue: out = gamma*O/l + x ----
    {
        int q0 = n0 + w * 16 + (lane >> 2);
        #pragma unroll
        for (int ct = 0; ct < 32; ct++) {
            int c0 = ct * 8 + 2 * (lane & 3);
            float ga = gamma[c0], gb = gamma[c0 + 1];
            size_t i00 = (size_t)(b * NI + c0) * NPIX + q0;
            out[i00]            = ga * oacc[ct][0] * linv[0] + x[i00];
            out[i00 + NPIX]     = gb * oacc[ct][1] * linv[0] + x[i00 + NPIX];
            out[i00 + 8]        = ga * oacc[ct][2] * linv[1] + x[i00 + 8];
            out[i00 + NPIX + 8] = gb * oacc[ct][3] * linv[1] + x[i00 + NPIX + 8];
        }
    }
}

// ---------------------------------------------------------------------------
extern "C" void kernel_launch(void* const* d_in, const int* in_sizes, int n_in,
                              void* d_out, int out_size)
{
    const float* x     = (const float*)d_in[0];
    const float* wq    = (const float*)d_in[1];
    const float* bq    = (const float*)d_in[2];
    const float* wk    = (const float*)d_in[3];
    const float* bk    = (const float*)d_in[4];
    const float* wv    = (const float*)d_in[5];
    const float* bv    = (const float*)d_in[6];
    const float* gamma = (const float*)d_in[7];
    float* out = (float*)d_out;

    cudaFuncSetAttribute(attn_kernel,
                         cudaFuncAttributeMaxDynamicSharedMemorySize, SMEM_BYTES);

    proj_all<<<dim3(80, BS), 256>>>(x, wq, bq, wk, bk, wv, bv);
    attn_kernel<<<dim3(NPIX / BM, BS), 256, SMEM_BYTES>>>(x, gamma, out);
}